// round 17
// baseline (speedup 1.0000x reference)
#include <cuda_runtime.h>
#include <cuda_fp16.h>
#include <cstdint>
#include <math.h>

#define SEQ    2048
#define HEADS  16
#define HD     64
#define EMB    1024
#define BATCH  4
#define ROWS   (BATCH * SEQ)   // 8192
#define SCALE  0.125f
#define MASKP  (-50.0f)
#define LOG2E  1.4426950408889634f
#define QC     (SCALE * LOG2E)          // folded into q at projection
#define MASK2  (MASKP * LOG2E)          // mask add in log2 domain

// Scratch (allocation-free rule: __device__ globals)
__device__ __half g_xh[ROWS * EMB];
__device__ __half g_qh[ROWS * EMB];
__device__ __half g_kh[ROWS * EMB];
__device__ __half g_vh[ROWS * EMB];
__device__ __half g_ah[ROWS * EMB];
__device__ __half g_wt[4][EMB * EMB];   // W transposed [N][K] fp16; [0..2] = Wq|Wk|Wv fused

// ---------------- PTX helpers ----------------------------------------------
__device__ __forceinline__ uint32_t smem_u32(const void* p) {
    uint32_t a;
    asm("{ .reg .u64 t; cvta.to.shared.u64 t, %1; cvt.u32.u64 %0, t; }"
        : "=r"(a) : "l"(p));
    return a;
}
__device__ __forceinline__ void ldsm4(uint32_t& r0, uint32_t& r1,
                                      uint32_t& r2, uint32_t& r3, uint32_t a) {
    asm volatile("ldmatrix.sync.aligned.m8n8.x4.shared.b16 {%0,%1,%2,%3}, [%4];"
                 : "=r"(r0), "=r"(r1), "=r"(r2), "=r"(r3) : "r"(a));
}
__device__ __forceinline__ void ldsm4t(uint32_t& r0, uint32_t& r1,
                                       uint32_t& r2, uint32_t& r3, uint32_t a) {
    asm volatile("ldmatrix.sync.aligned.m8n8.x4.trans.shared.b16 {%0,%1,%2,%3}, [%4];"
                 : "=r"(r0), "=r"(r1), "=r"(r2), "=r"(r3) : "r"(a));
}
__device__ __forceinline__ void mma_f16(float* c, const uint32_t* a,
                                        uint32_t b0, uint32_t b1) {
    asm volatile("mma.sync.aligned.m16n8k16.row.col.f32.f16.f16.f32 "
                 "{%0,%1,%2,%3}, {%4,%5,%6,%7}, {%8,%9}, {%0,%1,%2,%3};"
                 : "+f"(c[0]), "+f"(c[1]), "+f"(c[2]), "+f"(c[3])
                 : "r"(a[0]), "r"(a[1]), "r"(a[2]), "r"(a[3]), "r"(b0), "r"(b1));
}
__device__ __forceinline__ uint32_t pack_h2(float a, float b) {
    __half2 h = __floats2half2_rn(a, b);
    return (uint32_t)__half_as_ushort(__low2half(h)) |
           ((uint32_t)__half_as_ushort(__high2half(h)) << 16);
}
__device__ __forceinline__ uint32_t h2ex2(uint32_t a) {
    uint32_t d;
    asm volatile("ex2.approx.f16x2 %0, %1;" : "=r"(d) : "r"(a));
    return d;
}
#define CP_ASYNC16(da, ga) \
    asm volatile("cp.async.cg.shared.global [%0], [%1], 16;" :: "r"(da), "l"(ga))
#define CP_COMMIT() asm volatile("cp.async.commit_group;" ::: "memory")
template <int N> __device__ __forceinline__ void cp_wait() {
    asm volatile("cp.async.wait_group %0;" :: "n"(N) : "memory");
}

// ---------------- convert kernels ------------------------------------------
__global__ __launch_bounds__(256) void f2h_kernel(
    const float* __restrict__ in, __half* __restrict__ out, int n4)
{
    int i = blockIdx.x * blockDim.x + threadIdx.x;
    if (i >= n4) return;
    float4 v = ((const float4*)in)[i];
    __half2* dst = (__half2*)(out + 4 * (size_t)i);
    dst[0] = __floats2half2_rn(v.x, v.y);
    dst[1] = __floats2half2_rn(v.z, v.w);
}

// 4 weights W[k][n] -> Wt[n][k] fp16, z-batched
__global__ __launch_bounds__(256) void transpose_h4_kernel(
    const float* __restrict__ W0, const float* __restrict__ W1,
    const float* __restrict__ W2, const float* __restrict__ W3,
    __half* __restrict__ T)
{
    __shared__ float t[32][33];
    const float* W = (blockIdx.z == 0) ? W0 : (blockIdx.z == 1) ? W1
                   : (blockIdx.z == 2) ? W2 : W3;
    __half* Tz = T + (size_t)blockIdx.z * EMB * EMB;
    int n = blockIdx.x * 32 + threadIdx.x;
    int k = blockIdx.y * 32 + threadIdx.y;
    #pragma unroll
    for (int j = 0; j < 4; ++j)
        t[threadIdx.y + 8 * j][threadIdx.x] = W[(size_t)(k + 8 * j) * EMB + n];
    __syncthreads();
    int ko = blockIdx.y * 32 + threadIdx.x;
    int no = blockIdx.x * 32 + threadIdx.y;
    #pragma unroll
    for (int j = 0; j < 4; ++j)
        Tz[(size_t)(no + 8 * j) * EMB + ko] =
            __float2half(t[threadIdx.x][threadIdx.y + 8 * j]);
}

// ---------------------------------------------------------------------------
// fp16 mma GEMM v3: CTA tile 128x256, warp tile 64x64 (8 warps, 2x4),
// BK=64, 3-stage cp.async ring, ONE __syncthreads per K-chunk.
// MODE 0: fp32 out (N=1024). MODE 1: half out routed by bn/1024 (QKV, N=3072);
//         the q third (sel==0) is pre-scaled by QC = SCALE*log2e.
// ---------------------------------------------------------------------------
#define BK3    64
#define ROWB3  144                    // bytes per 64-half row (128B + 16B pad)
#define ATILE3 (128 * ROWB3)          // 18432
#define BTILE3 (256 * ROWB3)          // 36864
#define STAGE3 (ATILE3 + BTILE3)      // 55296
#define GSM3   (3 * STAGE3)           // 165888

template <int MODE>
__global__ __launch_bounds__(256, 1) void hgemm3(
    const __half* __restrict__ A, const __half* __restrict__ Bt,
    void* __restrict__ C0, void* __restrict__ C1, void* __restrict__ C2)
{
    extern __shared__ __align__(16) char smh3[];
    const uint32_t sb = smem_u32(smh3);
    const int tid  = threadIdx.x;
    const int lane = tid & 31, wid = tid >> 5;
    const int wm = (wid >> 2) * 64;       // 2 m-warps
    const int wn = (wid & 3) * 64;        // 4 n-warps
    const int bm = blockIdx.y * 128, bn = blockIdx.x * 256;

    const __half* Ab = A  + (size_t)bm * EMB;
    const __half* Bb = Bt + (size_t)bn * EMB;

    // per stage: A 128 rows + B 256 rows, each 8 x 16B segs
    #define LOADH3(k0, st) do {                                                \
        uint32_t base_ = sb + (st) * STAGE3;                                   \
        _Pragma("unroll")                                                      \
        for (int it_ = 0; it_ < 4; ++it_) {                                    \
            int v_ = it_ * 256 + tid;                                          \
            int r_ = v_ >> 3, s_ = v_ & 7;                                     \
            CP_ASYNC16(base_ + r_ * ROWB3 + s_ * 16,                           \
                       Ab + (size_t)r_ * EMB + (k0) + s_ * 8);                 \
        }                                                                      \
        _Pragma("unroll")                                                      \
        for (int it_ = 0; it_ < 8; ++it_) {                                    \
            int v_ = it_ * 256 + tid;                                          \
            int r_ = v_ >> 3, s_ = v_ & 7;                                     \
            CP_ASYNC16(base_ + ATILE3 + r_ * ROWB3 + s_ * 16,                  \
                       Bb + (size_t)r_ * EMB + (k0) + s_ * 8);                 \
        }                                                                      \
    } while (0)

    const int fr = ((lane >> 3) & 1) * 8 + (lane & 7);
    const int fk = (lane >> 4) * 8;

    float acc[4][8][4];
    #pragma unroll
    for (int i = 0; i < 4; ++i)
        #pragma unroll
        for (int j = 0; j < 8; ++j)
            #pragma unroll
            for (int e = 0; e < 4; ++e) acc[i][j][e] = 0.0f;

    LOADH3(0, 0);
    CP_COMMIT();
    LOADH3(BK3, 1);
    CP_COMMIT();

    const int NCH = EMB / BK3;   // 16
    for (int c = 0; c < NCH; ++c) {
        if (c + 1 < NCH) cp_wait<1>(); else cp_wait<0>();
        __syncthreads();
        // issue c+2 into stage (c+2)%3 — overwrites chunk c-1's stage, which
        // every warp finished before reaching the barrier above
        if (c + 2 < NCH) { LOADH3((c + 2) * BK3, (c + 2) % 3); CP_COMMIT(); }

        const uint32_t base = sb + (c % 3) * STAGE3;
        #pragma unroll
        for (int ks = 0; ks < 4; ++ks) {
            const int kb = ks * 16 + fk;
            uint32_t af[4][4];
            #pragma unroll
            for (int mt = 0; mt < 4; ++mt) {
                uint32_t ra = base + (wm + mt * 16 + fr) * ROWB3 + kb * 2;
                ldsm4(af[mt][0], af[mt][1], af[mt][2], af[mt][3], ra);
            }
            #pragma unroll
            for (int g = 0; g < 4; ++g) {
                uint32_t b0, b1, b2, b3;
                uint32_t rb = base + ATILE3 + (wn + g * 16 + fr) * ROWB3 + kb * 2;
                ldsm4(b0, b1, b2, b3, rb);
                #pragma unroll
                for (int mt = 0; mt < 4; ++mt) {
                    mma_f16(acc[mt][2 * g],     af[mt], b0, b2);
                    mma_f16(acc[mt][2 * g + 1], af[mt], b1, b3);
                }
            }
        }
    }

    const int g = lane >> 2, tg = lane & 3;
    if (MODE == 1) {
        const int sel = bn >> 10;
        __half* C = (__half*)(sel == 0 ? C0 : sel == 1 ? C1 : C2);
        const float fs = (sel == 0) ? QC : 1.0f;   // fold SCALE*log2e into q
        const int cb = (bn & 1023) + wn + tg * 2;
        #pragma unroll
        for (int mt = 0; mt < 4; ++mt)
            #pragma unroll
            for (int nt = 0; nt < 8; ++nt) {
                const size_t row = (size_t)(bm + wm + mt * 16 + g);
                *(uint32_t*)(C + row * EMB + cb + nt * 8) =
                    pack_h2(acc[mt][nt][0] * fs, acc[mt][nt][1] * fs);
                *(uint32_t*)(C + (row + 8) * EMB + cb + nt * 8) =
                    pack_h2(acc[mt][nt][2] * fs, acc[mt][nt][3] * fs);
            }
    } else {
        float* C = (float*)C0;
        const int cb = bn + wn + tg * 2;
        #pragma unroll
        for (int mt = 0; mt < 4; ++mt)
            #pragma unroll
            for (int nt = 0; nt < 8; ++nt) {
                const size_t row = (size_t)(bm + wm + mt * 16 + g);
                *(float2*)(C + row * EMB + cb + nt * 8) =
                    make_float2(acc[mt][nt][0], acc[mt][nt][1]);
                *(float2*)(C + (row + 8) * EMB + cb + nt * 8) =
                    make_float2(acc[mt][nt][2], acc[mt][nt][3]);
            }
    }
    #undef LOADH3
}

// ---------------------------------------------------------------------------
// FA2-style fp16 attention v3 (R15-proven): 3-stage cp.async ring,
// ex2.approx.f16x2 softmax (q pre-scaled), row sums via all-ones MMA.
// ---------------------------------------------------------------------------
#define TS 64
#define ARPB   144                      // bytes per smem row (128B data + 16B pad)
#define QBYTES (128 * ARPB)             // 18432
#define KVT    (TS * ARPB)              // 9216 per K or V tile
#define ASTAGE (2 * KVT)                // 18432 (K + V)
#define ASMEM  (QBYTES + 3 * ASTAGE)    // 73728

__global__ __launch_bounds__(256, 2) void attn_mma(
    const __half* __restrict__ Q, const __half* __restrict__ K,
    const __half* __restrict__ V, __half* __restrict__ O)
{
    extern __shared__ __align__(16) char sma[];
    const uint32_t sQ = smem_u32(sma);

    const int tid  = threadIdx.x;
    const int lane = tid & 31, wid = tid >> 5;
    const int qblk = blockIdx.x, h = blockIdx.y, b = blockIdx.z;
    const int q0   = qblk * 128;

    const size_t slice = (size_t)b * SEQ * EMB + (size_t)h * HD;
    const __half* Qg = Q + slice;
    const __half* Kg = K + slice;
    const __half* Vg = V + slice;
    __half*       Og = O + slice;

    #define LOADKV(k0, st) do {                                                \
        uint32_t kb_ = sQ + QBYTES + (st) * ASTAGE;                            \
        _Pragma("unroll")                                                      \
        for (int it_ = 0; it_ < 2; ++it_) {                                    \
            int v_ = it_ * 256 + tid;                                          \
            int r_ = v_ >> 3, s_ = v_ & 7;                                     \
            CP_ASYNC16(kb_ + r_ * ARPB + s_ * 16,                              \
                       Kg + (size_t)((k0) + r_) * EMB + s_ * 8);               \
            CP_ASYNC16(kb_ + KVT + r_ * ARPB + s_ * 16,                       \
                       Vg + (size_t)((k0) + r_) * EMB + s_ * 8);               \
        }                                                                      \
    } while (0)

    const int ntiles = 2 * qblk + 2;
    const int nfull  = 2 * qblk;

    #pragma unroll
    for (int it = 0; it < 4; ++it) {
        int v = it * 256 + tid;
        int r = v >> 3, seg = v & 7;
        CP_ASYNC16(sQ + r * ARPB + seg * 16,
                   Qg + (size_t)(q0 + r) * EMB + seg * 8);
    }
    LOADKV(0, 0);
    CP_COMMIT();
    LOADKV(TS, 1);
    CP_COMMIT();

    const int fr = ((lane >> 3) & 1) * 8 + (lane & 7);
    const int fk = (lane >> 4) * 8;

    uint32_t qf[4][4];
    float o[8][4];
    #pragma unroll
    for (int i = 0; i < 8; ++i)
        #pragma unroll
        for (int j = 0; j < 4; ++j) o[i][j] = 0.0f;
    float rsacc[4] = {0.0f, 0.0f, 0.0f, 0.0f};
    const uint32_t ONE2 = 0x3C003C00u;

    const int qr_lo = q0 + wid * 16 + (lane >> 2);
    const int qr_hi = qr_lo + 8;

    for (int t = 0; t < ntiles; ++t) {
        if (t + 1 < ntiles) cp_wait<1>(); else cp_wait<0>();
        __syncthreads();

        if (t == 0) {
            #pragma unroll
            for (int ks = 0; ks < 4; ++ks) {
                uint32_t addr = sQ + (wid * 16 + fr) * ARPB + (ks * 16 + fk) * 2;
                ldsm4(qf[ks][0], qf[ks][1], qf[ks][2], qf[ks][3], addr);
            }
        }
        if (t + 2 < ntiles) { LOADKV((t + 2) * TS, (t + 2) % 3); CP_COMMIT(); }

        const uint32_t sK = sQ + QBYTES + (t % 3) * ASTAGE;
        const uint32_t sV = sK + KVT;

        float sc[8][4];
        #pragma unroll
        for (int i = 0; i < 8; ++i)
            #pragma unroll
            for (int j = 0; j < 4; ++j) sc[i][j] = 0.0f;

        #pragma unroll
        for (int ks = 0; ks < 4; ++ks) {
            uint32_t bf[4][4];
            #pragma unroll
            for (int g = 0; g < 4; ++g) {
                uint32_t addr = sK + (g * 16 + fr) * ARPB + (ks * 16 + fk) * 2;
                ldsm4(bf[g][0], bf[g][1], bf[g][2], bf[g][3], addr);
            }
            #pragma unroll
            for (int nt = 0; nt < 8; ++nt)
                mma_f16(sc[nt], qf[ks], bf[nt >> 1][nt & 1], bf[nt >> 1][2 + (nt & 1)]);
        }

        uint32_t ph_lo[8], ph_hi[8];
        if (t < nfull) {
            #pragma unroll
            for (int nt = 0; nt < 8; ++nt) {
                ph_lo[nt] = h2ex2(pack_h2(sc[nt][0], sc[nt][1]));
                ph_hi[nt] = h2ex2(pack_h2(sc[nt][2], sc[nt][3]));
            }
        } else {
            const int kcb = t * TS + 2 * (lane & 3);
            #pragma unroll
            for (int nt = 0; nt < 8; ++nt) {
                int kc = kcb + nt * 8;
                float a0 = sc[nt][0] + (kc     > qr_lo ? MASK2 : 0.0f);
                float a1 = sc[nt][1] + (kc + 1 > qr_lo ? MASK2 : 0.0f);
                float a2 = sc[nt][2] + (kc     > qr_hi ? MASK2 : 0.0f);
                float a3 = sc[nt][3] + (kc + 1 > qr_hi ? MASK2 : 0.0f);
                ph_lo[nt] = h2ex2(pack_h2(a0, a1));
                ph_hi[nt] = h2ex2(pack_h2(a2, a3));
            }
        }

        #pragma unroll
        for (int j = 0; j < 4; ++j) {
            uint32_t af[4] = {ph_lo[2 * j], ph_hi[2 * j],
                              ph_lo[2 * j + 1], ph_hi[2 * j + 1]};
            #pragma unroll
            for (int g = 0; g < 4; ++g) {
                uint32_t vf0, vf1, vf2, vf3;
                uint32_t addr = sV + (j * 16 + fr) * ARPB + (g * 16 + fk) * 2;
                ldsm4t(vf0, vf1, vf2, vf3, addr);
                mma_f16(o[2 * g],     af, vf0, vf1);
                mma_f16(o[2 * g + 1], af, vf2, vf3);
            }
            mma_f16(rsacc, af, ONE2, ONE2);
        }
    }

    const float il = 1.0f / rsacc[0], ih = 1.0f / rsacc[2];

    #pragma unroll
    for (int nd = 0; nd < 8; ++nd) {
        int dc = nd * 8 + 2 * (lane & 3);
        *(uint32_t*)(Og + (size_t)qr_lo * EMB + dc) = pack_h2(o[nd][0] * il, o[nd][1] * il);
        *(uint32_t*)(Og + (size_t)qr_hi * EMB + dc) = pack_h2(o[nd][2] * ih, o[nd][3] * ih);
    }
    #undef LOADKV
}

// ---------------------------------------------------------------------------
extern "C" void kernel_launch(void* const* d_in, const int* in_sizes, int n_in,
                              void* d_out, int out_size)
{
    const float* x  = (const float*)d_in[0];
    const float* Wq = (const float*)d_in[1];
    const float* Wk = (const float*)d_in[2];
    const float* Wv = (const float*)d_in[3];
    const float* Wr = (const float*)d_in[4];

    __half *xh, *qh, *kh, *vh, *ah, *wt;
    cudaGetSymbolAddress((void**)&xh, g_xh);
    cudaGetSymbolAddress((void**)&qh, g_qh);
    cudaGetSymbolAddress((void**)&kh, g_kh);
    cudaGetSymbolAddress((void**)&vh, g_vh);
    cudaGetSymbolAddress((void**)&ah, g_ah);
    cudaGetSymbolAddress((void**)&wt, g_wt);

    cudaFuncSetAttribute(hgemm3<0>, cudaFuncAttributeMaxDynamicSharedMemorySize, GSM3);
    cudaFuncSetAttribute(hgemm3<1>, cudaFuncAttributeMaxDynamicSharedMemorySize, GSM3);
    cudaFuncSetAttribute(attn_mma,  cudaFuncAttributeMaxDynamicSharedMemorySize, ASMEM);

    // converts
    f2h_kernel<<<(ROWS * EMB / 4 + 255) / 256, 256>>>(x, xh, ROWS * EMB / 4);
    transpose_h4_kernel<<<dim3(32, 32, 4), dim3(32, 8)>>>(Wq, Wk, Wv, Wr, wt);

    // fused QKV projection: N = 3072 (q pre-scaled by SCALE*log2e)
    hgemm3<1><<<dim3(12, 64), 256, GSM3>>>(xh, wt, qh, kh, vh);

    attn_mma<<<dim3(SEQ / 128, HEADS, BATCH), 256, ASMEM>>>(qh, kh, vh, ah);

    // output projection: fp32 out
    hgemm3<0><<<dim3(4, 64), 256, GSM3>>>(ah, wt + 3 * (size_t)EMB * EMB,
                                          d_out, nullptr, nullptr);
}